// round 1
// baseline (speedup 1.0000x reference)
#include <cuda_runtime.h>

// CLSTM cell: z = [X] @ W_combined^T  (M=4096, N=8192, K=4096), then pointwise gates.
//
// X columns:   [0,1024)=xr  [1024,2048)=xi  [2048,3072)=hr  [3072,4096)=hi
//   (xr|xi is exactly the `input` row; hr|hi is exactly the `h_x` row)
// Output cols: n = ri*4096 + g*1024 + o
//   ri=0 (real): segs -> +Uw_r, -Uw_i, +Ww_r, -Ww_i
//   ri=1 (imag): segs -> +Uw_i, +Uw_r, +Ww_i, +Ww_r
// Biases added in epilogue.

#define BDIM 4096
#define HDIM 1024
#define KTOT 4096
#define NTOT 8192

// 134 MB scratch for z (allowed: static __device__ array, no runtime alloc)
__device__ float g_z[(size_t)BDIM * NTOT];

__global__ __launch_bounds__(256, 2)
void clstm_gemm_kernel(const float* __restrict__ input,
                       const float* __restrict__ h_x,
                       const float* __restrict__ Uw_r,
                       const float* __restrict__ Uw_i,
                       const float* __restrict__ Ww_r,
                       const float* __restrict__ Ww_i)
{
    __shared__ float As[16][128];
    __shared__ float Bs[16][128];

    const int tid = threadIdx.x;
    const int n0 = blockIdx.x * 128;   // output-column tile
    const int m0 = blockIdx.y * 128;   // batch-row tile

    const int ri    = n0 >> 12;         // 0 = real part, 1 = imag part
    const int g     = (n0 & 4095) >> 10;
    const int nloc0 = n0 & 1023;        // o offset within the gate block

    // Per-K-segment weight source + sign
    const float* wseg[4];
    float sgn[4];
    if (ri == 0) {
        wseg[0] = Uw_r; sgn[0] =  1.0f;
        wseg[1] = Uw_i; sgn[1] = -1.0f;
        wseg[2] = Ww_r; sgn[2] =  1.0f;
        wseg[3] = Ww_i; sgn[3] = -1.0f;
    } else {
        wseg[0] = Uw_i; sgn[0] =  1.0f;
        wseg[1] = Uw_r; sgn[1] =  1.0f;
        wseg[2] = Ww_i; sgn[2] =  1.0f;
        wseg[3] = Ww_r; sgn[3] =  1.0f;
    }
    const size_t wbase_off = (size_t)g * HDIM * 1024 + (size_t)nloc0 * 1024;

    const int ty = tid >> 4;   // 0..15 (M direction)
    const int tx = tid & 15;   // 0..15 (N direction)

    float acc[8][8];
#pragma unroll
    for (int i = 0; i < 8; i++)
#pragma unroll
        for (int j = 0; j < 8; j++) acc[i][j] = 0.0f;

    for (int k0 = 0; k0 < KTOT; k0 += 16) {
        const int seg = k0 >> 10;
        const float* asrc = (seg < 2) ? input : h_x;
        const int acol = k0 & 2047;
        const float* wptr = wseg[seg] + wbase_off + (k0 & 1023);
        const float s = sgn[seg];

        // Load 128x16 tiles of A and B (transposed into [k][row] shared layout).
        // task -> (kv fast, row slow) so global loads are 64B-contiguous per row group.
#pragma unroll
        for (int i = 0; i < 2; i++) {
            const int task = tid + 256 * i;      // 0..511
            const int kv = task & 3;             // which float4 along k
            const int r  = task >> 2;            // 0..127 row within tile

            float4 av = *reinterpret_cast<const float4*>(
                asrc + (size_t)(m0 + r) * 2048 + acol + kv * 4);
            As[kv * 4 + 0][r] = av.x;
            As[kv * 4 + 1][r] = av.y;
            As[kv * 4 + 2][r] = av.z;
            As[kv * 4 + 3][r] = av.w;

            float4 bv = *reinterpret_cast<const float4*>(
                wptr + (size_t)r * 1024 + kv * 4);
            Bs[kv * 4 + 0][r] = s * bv.x;
            Bs[kv * 4 + 1][r] = s * bv.y;
            Bs[kv * 4 + 2][r] = s * bv.z;
            Bs[kv * 4 + 3][r] = s * bv.w;
        }
        __syncthreads();

#pragma unroll
        for (int kk = 0; kk < 16; kk++) {
            float4 a0 = *reinterpret_cast<const float4*>(&As[kk][ty * 8]);
            float4 a1 = *reinterpret_cast<const float4*>(&As[kk][ty * 8 + 4]);
            float4 b0 = *reinterpret_cast<const float4*>(&Bs[kk][tx * 8]);
            float4 b1 = *reinterpret_cast<const float4*>(&Bs[kk][tx * 8 + 4]);
            float a[8] = {a0.x, a0.y, a0.z, a0.w, a1.x, a1.y, a1.z, a1.w};
            float b[8] = {b0.x, b0.y, b0.z, b0.w, b1.x, b1.y, b1.z, b1.w};
#pragma unroll
            for (int i = 0; i < 8; i++)
#pragma unroll
                for (int j = 0; j < 8; j++)
                    acc[i][j] = fmaf(a[i], b[j], acc[i][j]);
        }
        __syncthreads();
    }

    // Write z tile (no bias here; epilogue adds it)
#pragma unroll
    for (int i = 0; i < 8; i++) {
        const size_t row = (size_t)(m0 + ty * 8 + i) * NTOT + n0 + tx * 8;
        float4 v0 = make_float4(acc[i][0], acc[i][1], acc[i][2], acc[i][3]);
        float4 v1 = make_float4(acc[i][4], acc[i][5], acc[i][6], acc[i][7]);
        *reinterpret_cast<float4*>(&g_z[row])     = v0;
        *reinterpret_cast<float4*>(&g_z[row + 4]) = v1;
    }
}

__device__ __forceinline__ float sigmoidf_(float x) {
    return 1.0f / (1.0f + expf(-x));
}

__global__ __launch_bounds__(256)
void clstm_epilogue_kernel(const float* __restrict__ c_x,
                           const float* __restrict__ Ub_r,
                           const float* __restrict__ Ub_i,
                           const float* __restrict__ Wb_r,
                           const float* __restrict__ Wb_i,
                           float* __restrict__ out)
{
    const int idx = blockIdx.x * blockDim.x + threadIdx.x;  // 0 .. B*H-1
    const int b = idx >> 10;
    const int o = idx & 1023;

    const float* z = g_z + (size_t)b * NTOT;

    float zr[4], zi[4];
#pragma unroll
    for (int gg = 0; gg < 4; gg++) {
        const int go = gg * 1024 + o;
        zr[gg] = z[go]        + Ub_r[go] + Wb_r[go];
        zi[gg] = z[4096 + go] + Ub_i[go] + Wb_i[go];
    }

    const float fr = sigmoidf_(zr[0]), fi = sigmoidf_(zi[0]);
    const float ir = sigmoidf_(zr[1]), ii = sigmoidf_(zi[1]);
    const float ar = tanhf(zr[2]),     ai = tanhf(zi[2]);
    const float orr = sigmoidf_(zr[3]), oi = sigmoidf_(zi[3]);

    const float cr = c_x[(size_t)b * 2048 + o];
    const float ci = c_x[(size_t)b * 2048 + 1024 + o];

    const float ct_r = (cr * fr - ci * fi) + (ar * ir - ai * ii);
    const float ct_i = (cr * fi + ci * fr) + (ar * ii + ai * ir);

    const float tr = tanhf(ct_r);
    const float ti = tanhf(ct_i);
    const float ht_r = orr * tr - oi * ti;
    const float ht_i = orr * ti + oi * tr;

    const size_t hrow = (size_t)b * 2048;
    const size_t coff = (size_t)BDIM * 2048;
    out[hrow + o]               = ht_r;
    out[hrow + 1024 + o]        = ht_i;
    out[coff + hrow + o]        = ct_r;
    out[coff + hrow + 1024 + o] = ct_i;
}

extern "C" void kernel_launch(void* const* d_in, const int* in_sizes, int n_in,
                              void* d_out, int out_size)
{
    const float* input = (const float*)d_in[0];
    const float* h_x   = (const float*)d_in[1];
    const float* c_x   = (const float*)d_in[2];
    const float* Uw_r  = (const float*)d_in[3];
    const float* Uw_i  = (const float*)d_in[4];
    const float* Ub_r  = (const float*)d_in[5];
    const float* Ub_i  = (const float*)d_in[6];
    const float* Ww_r  = (const float*)d_in[7];
    const float* Ww_i  = (const float*)d_in[8];
    const float* Wb_r  = (const float*)d_in[9];
    const float* Wb_i  = (const float*)d_in[10];
    float* out = (float*)d_out;

    dim3 grid(NTOT / 128, BDIM / 128);  // (64, 32)
    clstm_gemm_kernel<<<grid, 256>>>(input, h_x, Uw_r, Uw_i, Ww_r, Ww_i);

    clstm_epilogue_kernel<<<(BDIM * HDIM) / 256, 256>>>(c_x, Ub_r, Ub_i, Wb_r, Wb_i, out);
}

// round 3
// speedup vs baseline: 7.4671x; 7.4671x over previous
#include <cuda_runtime.h>
#include <cuda_bf16.h>

// CLSTM cell, tensor-core GEMM with dual compile paths:
//  - sm_103a pass (__CUDA_ARCH_FEAT_SM103_ALL): tcgen05 bf16 SS MMA, TMEM accum
//  - plain sm_103 pass: mma.sync m16n8k16 bf16 (HMMA) with cp.async pipeline
// z = [xr|xi|hr|hi] @ Wcomb^T  (M=4096, N=8192, K=4096), fp32 via bf16 hi/lo 3-term.

#define BDIM 4096
#define HDIM 1024
#define KTOT 4096
#define NTOT 8192

// ---------------- static device scratch ----------------
__device__ __align__(256) __nv_bfloat16 g_Ah[(size_t)BDIM * KTOT];
__device__ __align__(256) __nv_bfloat16 g_Al[(size_t)BDIM * KTOT];
__device__ __align__(256) __nv_bfloat16 g_Bh[(size_t)NTOT * KTOT];
__device__ __align__(256) __nv_bfloat16 g_Bl[(size_t)NTOT * KTOT];
__device__ float g_z[(size_t)BDIM * NTOT];

// ---------------- common helpers ----------------
__device__ __forceinline__ unsigned smem_to_u32(const void* p) {
    unsigned a;
    asm("{ .reg .u64 t; cvta.to.shared.u64 t, %1; cvt.u32.u64 %0, t; }"
        : "=r"(a) : "l"(p));
    return a;
}
__device__ __forceinline__ void cp_async16(unsigned dst, const void* src) {
    asm volatile("cp.async.cg.shared.global [%0], [%1], 16;"
        :: "r"(dst), "l"(src) : "memory");
}
#define CP_COMMIT() asm volatile("cp.async.commit_group;" ::: "memory")
#define CP_WAIT1()  asm volatile("cp.async.wait_group 1;" ::: "memory")

#define SMEM_BYTES 133120

// ============================================================
//                     GEMM kernel
// ============================================================
__global__ __launch_bounds__(256, 1)
void clstm_tc_gemm_kernel() {
    extern __shared__ char dsm[];

#ifdef __CUDA_ARCH_FEAT_SM103_ALL
    // ================= tcgen05 path (sm_103a) =================
    // K-chunk 64, 2 stages; stage = Ah16K|Al16K|Bh16K|Bl16K = 64KB
    #define KCH 64
    #define NCHUNK (KTOT / KCH)
    #define STAGE_BYTES 65536
    #define A_H 0
    #define A_L 16384
    #define B_H 32768
    #define B_L 49152
    // idesc: dtype=F32, a/btype=BF16, N=128, M=128
    #define IDESC128 ((1u << 4) | (1u << 7) | (1u << 10) | (16u << 17) | (8u << 24))

    const unsigned base = smem_to_u32(dsm);
    const unsigned ctrl = base;
    const unsigned tiles = (base + 1024 + 1023) & ~1023u;

    const unsigned full0 = ctrl + 0, full1 = ctrl + 8;
    const unsigned emp0 = ctrl + 16, emp1 = ctrl + 24;
    const unsigned done = ctrl + 32;
    const unsigned tptr = ctrl + 40;

    const int tid = threadIdx.x;
    const int wid = tid >> 5;
    const unsigned m0 = blockIdx.y * 128;
    const unsigned n0 = blockIdx.x * 128;

    #define MBAR_INIT(a, c) \
        asm volatile("mbarrier.init.shared.b64 [%0], %1;" :: "r"(a), "r"((unsigned)(c)) : "memory")
    #define MBAR_WAIT(a, ph) do {                                                   \
        asm volatile("{\n\t.reg .pred P1;\n\t"                                      \
            "WL_%=:\n\t"                                                            \
            "mbarrier.try_wait.parity.acquire.cta.shared::cta.b64 P1, [%0], %1, 0x989680;\n\t" \
            "@P1 bra.uni WD_%=;\n\t"                                                \
            "bra.uni WL_%=;\n\t"                                                    \
            "WD_%=:\n\t}"                                                           \
            :: "r"(a), "r"((unsigned)(ph)) : "memory");                             \
    } while (0)

    if (tid == 0) {
        MBAR_INIT(full0, 128); MBAR_INIT(full1, 128);
        MBAR_INIT(emp0, 1);    MBAR_INIT(emp1, 1);
        MBAR_INIT(done, 1);
    }
    if (wid == 4)
        asm volatile("tcgen05.alloc.cta_group::1.sync.aligned.shared::cta.b32 [%0], %1;"
            :: "r"(tptr), "r"(512u) : "memory");
    __syncthreads();

    unsigned tmem;
    asm volatile("ld.shared.b32 %0, [%1];" : "=r"(tmem) : "r"(tptr));

    if (tid < 128) {
        // ---- loader warpgroup ----
        for (int i = 0; i < NCHUNK; i++) {
            const int s = i & 1, w = i >> 1;
            const unsigned fullb = s ? full1 : full0;
            const unsigned empb  = s ? emp1  : emp0;
            if (w >= 1) MBAR_WAIT(empb, (w - 1) & 1);
            const unsigned sb = tiles + s * STAGE_BYTES;
            const unsigned k0 = i * KCH;
#pragma unroll
            for (int it = 0; it < 16; it++) {   // A (hi+lo): 2048 x 16B
                const unsigned t2 = tid + 128 * it;
                const unsigned hl = t2 >> 10, rem = t2 & 1023;
                const unsigned r = rem >> 3, u = rem & 7;
                const __nv_bfloat16* src = (hl ? g_Al : g_Ah)
                    + (size_t)(m0 + r) * KTOT + k0 + u * 8;
                unsigned off = r * 128 + u * 16;
                off ^= (off >> 3) & 0x70;
                cp_async16(sb + A_H + hl * 16384 + off, src);
            }
#pragma unroll
            for (int it = 0; it < 16; it++) {   // B (hi+lo): 2048 x 16B
                const unsigned t3 = tid + 128 * it;
                const unsigned hl = t3 >> 10, rem = t3 & 1023;
                const unsigned r = rem >> 3, u = rem & 7;
                const __nv_bfloat16* src = (hl ? g_Bl : g_Bh)
                    + (size_t)(n0 + r) * KTOT + k0 + u * 8;
                unsigned off = r * 128 + u * 16;
                off ^= (off >> 3) & 0x70;
                cp_async16(sb + B_H + hl * 16384 + off, src);
            }
            asm volatile("cp.async.mbarrier.arrive.noinc.shared::cta.b64 [%0];"
                :: "r"(fullb) : "memory");
        }
    } else if (tid == 128) {
        // ---- MMA issue thread ----
        const unsigned long long DBASE =
            (2ull << 61) | (1ull << 46) | (64ull << 32) | (1ull << 16);
        for (int i = 0; i < NCHUNK; i++) {
            const int s = i & 1, w = i >> 1;
            const unsigned fullb = s ? full1 : full0;
            const unsigned empb  = s ? emp1  : emp0;
            MBAR_WAIT(fullb, w & 1);
            asm volatile("fence.proxy.async.shared::cta;" ::: "memory");
            const unsigned sb = tiles + s * STAGE_BYTES;
            const unsigned long long ah = DBASE | ((unsigned long long)((sb + A_H) >> 4) & 0x3FFF);
            const unsigned long long al = DBASE | ((unsigned long long)((sb + A_L) >> 4) & 0x3FFF);
            const unsigned long long bh = DBASE | ((unsigned long long)((sb + B_H) >> 4) & 0x3FFF);
            const unsigned long long bl = DBASE | ((unsigned long long)((sb + B_L) >> 4) & 0x3FFF);
#pragma unroll
            for (int ks = 0; ks < 4; ks++) {
                const unsigned en = (i == 0 && ks == 0) ? 0u : 1u;
                asm volatile("{\n\t.reg .pred p;\n\tsetp.ne.u32 p, %4, 0;\n\t"
                    "tcgen05.mma.cta_group::1.kind::f16 [%0], %1, %2, %3, {%5, %5, %5, %5}, p;\n\t}"
                    :: "r"(tmem), "l"(ah + ks * 2), "l"(bh + ks * 2), "r"(IDESC128),
                       "r"(en), "r"(0u) : "memory");
            }
#pragma unroll
            for (int ks = 0; ks < 4; ks++)
                asm volatile("{\n\t.reg .pred p;\n\tsetp.ne.u32 p, %4, 0;\n\t"
                    "tcgen05.mma.cta_group::1.kind::f16 [%0], %1, %2, %3, {%5, %5, %5, %5}, p;\n\t}"
                    :: "r"(tmem), "l"(ah + ks * 2), "l"(bl + ks * 2), "r"(IDESC128),
                       "r"(1u), "r"(0u) : "memory");
#pragma unroll
            for (int ks = 0; ks < 4; ks++)
                asm volatile("{\n\t.reg .pred p;\n\tsetp.ne.u32 p, %4, 0;\n\t"
                    "tcgen05.mma.cta_group::1.kind::f16 [%0], %1, %2, %3, {%5, %5, %5, %5}, p;\n\t}"
                    :: "r"(tmem), "l"(al + ks * 2), "l"(bh + ks * 2), "r"(IDESC128),
                       "r"(1u), "r"(0u) : "memory");
            asm volatile("tcgen05.commit.cta_group::1.mbarrier::arrive::one.shared::cluster.b64 [%0];"
                :: "r"(empb) : "memory");
        }
        asm volatile("tcgen05.commit.cta_group::1.mbarrier::arrive::one.shared::cluster.b64 [%0];"
            :: "r"(done) : "memory");
        MBAR_WAIT(done, 0);
    }
    __syncthreads();

    // ---- TMEM -> g_z (warps 0..3, 128 rows x 128 cols fp32) ----
    if (tid < 128) {
        asm volatile("tcgen05.fence::after_thread_sync;" ::: "memory");
        const int lid = tid & 31;
        const unsigned woff = ((unsigned)(tid >> 5)) << 21;
        float* rowp = g_z + (size_t)(m0 + (tid >> 5) * 32 + lid) * NTOT + n0;
#pragma unroll
        for (int j = 0; j < 4; j++) {
            unsigned r[32];
            asm volatile("tcgen05.ld.sync.aligned.32x32b.x32.b32 "
                "{%0, %1, %2, %3, %4, %5, %6, %7, "
                " %8, %9, %10, %11, %12, %13, %14, %15, "
                " %16, %17, %18, %19, %20, %21, %22, %23, "
                " %24, %25, %26, %27, %28, %29, %30, %31}, [%32];"
                : "=r"(r[0]),  "=r"(r[1]),  "=r"(r[2]),  "=r"(r[3]),
                  "=r"(r[4]),  "=r"(r[5]),  "=r"(r[6]),  "=r"(r[7]),
                  "=r"(r[8]),  "=r"(r[9]),  "=r"(r[10]), "=r"(r[11]),
                  "=r"(r[12]), "=r"(r[13]), "=r"(r[14]), "=r"(r[15]),
                  "=r"(r[16]), "=r"(r[17]), "=r"(r[18]), "=r"(r[19]),
                  "=r"(r[20]), "=r"(r[21]), "=r"(r[22]), "=r"(r[23]),
                  "=r"(r[24]), "=r"(r[25]), "=r"(r[26]), "=r"(r[27]),
                  "=r"(r[28]), "=r"(r[29]), "=r"(r[30]), "=r"(r[31])
                : "r"(tmem + woff + j * 32));
            asm volatile("tcgen05.wait::ld.sync.aligned;" ::: "memory");
#pragma unroll
            for (int c4 = 0; c4 < 8; c4++) {
                float4 v = make_float4(__uint_as_float(r[c4 * 4 + 0]),
                                       __uint_as_float(r[c4 * 4 + 1]),
                                       __uint_as_float(r[c4 * 4 + 2]),
                                       __uint_as_float(r[c4 * 4 + 3]));
                *reinterpret_cast<float4*>(rowp + j * 32 + c4 * 4) = v;
            }
        }
        asm volatile("tcgen05.fence::before_thread_sync;" ::: "memory");
    }
    __syncthreads();
    if (wid == 4) {
        asm volatile("tcgen05.relinquish_alloc_permit.cta_group::1.sync.aligned;");
        asm volatile("tcgen05.dealloc.cta_group::1.sync.aligned.b32 %0, %1;"
            :: "r"(tmem), "r"(512u));
    }

#else
    // ================= HMMA fallback path (plain sm_103) =================
    // CTA 128x128, K-chunk 32, 3-stage cp.async pipeline.
    // Smem rows padded 64B->80B (stride 80: 8 consecutive rows hit distinct banks).
    #define HKC 32
    #define HNCH (KTOT / HKC)     // 128
    #define HSTG 40960
    #define HA_H 0
    #define HA_L 10240
    #define HB_H 20480
    #define HB_L 30720
    #define RST 80

    const int tid = threadIdx.x;
    const int lane = tid & 31;
    const int w = tid >> 5;
    const unsigned m0 = blockIdx.y * 128;
    const unsigned n0 = blockIdx.x * 128;
    const unsigned base = smem_to_u32(dsm);
    const unsigned m_base = (unsigned)(w & 1) * 64;
    const unsigned n_base = (unsigned)(w >> 1) * 32;

    float acc[4][4][4];
#pragma unroll
    for (int a = 0; a < 4; a++)
#pragma unroll
        for (int b = 0; b < 4; b++)
#pragma unroll
            for (int c = 0; c < 4; c++) acc[a][b][c] = 0.0f;

    // stage loader: 2048 x 16B chunks over 256 threads
    auto load_stage = [&](unsigned sb, unsigned k0) {
#pragma unroll
        for (int it = 0; it < 8; it++) {
            const unsigned idx = (unsigned)tid + 256u * it;
            const unsigned mat = idx >> 9;
            const unsigned rem = idx & 511;
            const unsigned row = rem >> 2;
            const unsigned c = rem & 3;
            const __nv_bfloat16* src;
            if (mat == 0)      src = g_Ah + (size_t)(m0 + row) * KTOT + k0 + c * 8;
            else if (mat == 1) src = g_Al + (size_t)(m0 + row) * KTOT + k0 + c * 8;
            else if (mat == 2) src = g_Bh + (size_t)(n0 + row) * KTOT + k0 + c * 8;
            else               src = g_Bl + (size_t)(n0 + row) * KTOT + k0 + c * 8;
            cp_async16(sb + mat * 10240 + row * RST + c * 16, src);
        }
    };

    #define LDSM_X4(r0, r1, r2, r3, addr) \
        asm volatile("ldmatrix.sync.aligned.m8n8.x4.shared.b16 {%0,%1,%2,%3}, [%4];" \
            : "=r"(r0), "=r"(r1), "=r"(r2), "=r"(r3) : "r"(addr))
    #define LDSM_X2(r0, r1, addr) \
        asm volatile("ldmatrix.sync.aligned.m8n8.x2.shared.b16 {%0,%1}, [%2];" \
            : "=r"(r0), "=r"(r1) : "r"(addr))
    #define MMA_BF16(ac, av, bv) \
        asm volatile("mma.sync.aligned.m16n8k16.row.col.f32.bf16.bf16.f32 " \
            "{%0,%1,%2,%3}, {%4,%5,%6,%7}, {%8,%9}, {%0,%1,%2,%3};" \
            : "+f"((ac)[0]), "+f"((ac)[1]), "+f"((ac)[2]), "+f"((ac)[3]) \
            : "r"((av)[0]), "r"((av)[1]), "r"((av)[2]), "r"((av)[3]), \
              "r"((bv)[0]), "r"((bv)[1]))

    load_stage(base + 0 * HSTG, 0);  CP_COMMIT();
    load_stage(base + 1 * HSTG, HKC); CP_COMMIT();

    for (int i = 0; i < HNCH; i++) {
        CP_WAIT1();
        __syncthreads();
        if (i + 2 < HNCH) load_stage(base + (unsigned)((i + 2) % 3) * HSTG, (i + 2) * HKC);
        CP_COMMIT();

        const unsigned sb = base + (unsigned)(i % 3) * HSTG;
#pragma unroll
        for (int ks = 0; ks < 2; ks++) {
            unsigned a[4][4], bh[4][2], bl[4][2];
            const unsigned acol = (unsigned)(ks * 2 + (lane >> 4)) * 16;
            const unsigned bcol = (unsigned)(ks * 2 + ((lane >> 3) & 1)) * 16;
#pragma unroll
            for (int mt = 0; mt < 4; mt++) {
                const unsigned ad = sb + HA_H
                    + (m_base + mt * 16 + (lane & 15)) * RST + acol;
                LDSM_X4(a[mt][0], a[mt][1], a[mt][2], a[mt][3], ad);
            }
#pragma unroll
            for (int nt = 0; nt < 4; nt++) {
                const unsigned brow = (n_base + nt * 8 + (lane & 7)) * RST + bcol;
                LDSM_X2(bh[nt][0], bh[nt][1], sb + HB_H + brow);
                LDSM_X2(bl[nt][0], bl[nt][1], sb + HB_L + brow);
            }
#pragma unroll
            for (int mt = 0; mt < 4; mt++)
#pragma unroll
                for (int nt = 0; nt < 4; nt++) {
                    MMA_BF16(acc[mt][nt], a[mt], bh[nt]);
                    MMA_BF16(acc[mt][nt], a[mt], bl[nt]);
                }
            // reload A regs with Al, third term
#pragma unroll
            for (int mt = 0; mt < 4; mt++) {
                const unsigned ad = sb + HA_L
                    + (m_base + mt * 16 + (lane & 15)) * RST + acol;
                LDSM_X4(a[mt][0], a[mt][1], a[mt][2], a[mt][3], ad);
            }
#pragma unroll
            for (int mt = 0; mt < 4; mt++)
#pragma unroll
                for (int nt = 0; nt < 4; nt++)
                    MMA_BF16(acc[mt][nt], a[mt], bh[nt]);
        }
        __syncthreads();
    }

    // write accumulators to g_z
#pragma unroll
    for (int mt = 0; mt < 4; mt++) {
        const unsigned row0 = m0 + m_base + mt * 16 + (lane >> 2);
#pragma unroll
        for (int nt = 0; nt < 4; nt++) {
            const unsigned col = n0 + n_base + nt * 8 + 2 * (lane & 3);
            *reinterpret_cast<float2*>(&g_z[(size_t)row0 * NTOT + col]) =
                make_float2(acc[mt][nt][0], acc[mt][nt][1]);
            *reinterpret_cast<float2*>(&g_z[(size_t)(row0 + 8) * NTOT + col]) =
                make_float2(acc[mt][nt][2], acc[mt][nt][3]);
        }
    }
#endif
}

// ---------------- prep kernels ----------------
__device__ __forceinline__ void split_bf16(float v, __nv_bfloat16& hi, __nv_bfloat16& lo) {
    hi = __float2bfloat16_rn(v);
    lo = __float2bfloat16_rn(v - __bfloat162float(hi));
}

__global__ __launch_bounds__(256)
void prep_act_kernel(const float* __restrict__ input, const float* __restrict__ h_x) {
    const unsigned idx = blockIdx.x * 256 + threadIdx.x;
    const unsigned m = idx >> 10;
    const unsigned k = (idx & 1023) * 4;
    const float* src = (k < 2048) ? (input + (size_t)m * 2048 + k)
                                  : (h_x   + (size_t)m * 2048 + (k - 2048));
    float4 v = *reinterpret_cast<const float4*>(src);
    union { __nv_bfloat16 b[4]; uint2 u; } ph, pl;
    split_bf16(v.x, ph.b[0], pl.b[0]);
    split_bf16(v.y, ph.b[1], pl.b[1]);
    split_bf16(v.z, ph.b[2], pl.b[2]);
    split_bf16(v.w, ph.b[3], pl.b[3]);
    const size_t off = (size_t)m * KTOT + k;
    *reinterpret_cast<uint2*>(&g_Ah[off]) = ph.u;
    *reinterpret_cast<uint2*>(&g_Al[off]) = pl.u;
}

__global__ __launch_bounds__(256)
void prep_w_kernel(const float* __restrict__ Uw_r, const float* __restrict__ Uw_i,
                   const float* __restrict__ Ww_r, const float* __restrict__ Ww_i) {
    const unsigned idx = blockIdx.x * 256 + threadIdx.x;
    const unsigned n = idx >> 10;
    const unsigned k = (idx & 1023) * 4;
    const unsigned ri = n >> 12, g = (n >> 10) & 3, o = n & 1023;
    const unsigned seg = k >> 10, kk = k & 1023;

    const float* src;
    float s;
    if (ri == 0) {
        switch (seg) {
            case 0: src = Uw_r; s =  1.0f; break;
            case 1: src = Uw_i; s = -1.0f; break;
            case 2: src = Ww_r; s =  1.0f; break;
            default: src = Ww_i; s = -1.0f; break;
        }
    } else {
        switch (seg) {
            case 0: src = Uw_i; s = 1.0f; break;
            case 1: src = Uw_r; s = 1.0f; break;
            case 2: src = Ww_i; s = 1.0f; break;
            default: src = Ww_r; s = 1.0f; break;
        }
    }
    float4 v = *reinterpret_cast<const float4*>(src + ((size_t)(g * 1024 + o)) * 1024 + kk);
    union { __nv_bfloat16 b[4]; uint2 u; } ph, pl;
    split_bf16(s * v.x, ph.b[0], pl.b[0]);
    split_bf16(s * v.y, ph.b[1], pl.b[1]);
    split_bf16(s * v.z, ph.b[2], pl.b[2]);
    split_bf16(s * v.w, ph.b[3], pl.b[3]);
    const size_t off = (size_t)n * KTOT + k;
    *reinterpret_cast<uint2*>(&g_Bh[off]) = ph.u;
    *reinterpret_cast<uint2*>(&g_Bl[off]) = pl.u;
}

// ---------------- pointwise epilogue ----------------
__device__ __forceinline__ float sigmoidf_(float x) {
    return 1.0f / (1.0f + expf(-x));
}

__global__ __launch_bounds__(256)
void clstm_epilogue_kernel(const float* __restrict__ c_x,
                           const float* __restrict__ Ub_r,
                           const float* __restrict__ Ub_i,
                           const float* __restrict__ Wb_r,
                           const float* __restrict__ Wb_i,
                           float* __restrict__ out)
{
    const int idx = blockIdx.x * blockDim.x + threadIdx.x;
    const int b = idx >> 10;
    const int o = idx & 1023;

    const float* z = g_z + (size_t)b * NTOT;

    float zr[4], zi[4];
#pragma unroll
    for (int gg = 0; gg < 4; gg++) {
        const int go = gg * 1024 + o;
        zr[gg] = z[go]        + Ub_r[go] + Wb_r[go];
        zi[gg] = z[4096 + go] + Ub_i[go] + Wb_i[go];
    }

    const float fr = sigmoidf_(zr[0]), fi = sigmoidf_(zi[0]);
    const float ir = sigmoidf_(zr[1]), ii = sigmoidf_(zi[1]);
    const float ar = tanhf(zr[2]),     ai = tanhf(zi[2]);
    const float orr = sigmoidf_(zr[3]), oi = sigmoidf_(zi[3]);

    const float cr = c_x[(size_t)b * 2048 + o];
    const float ci = c_x[(size_t)b * 2048 + 1024 + o];

    const float ct_r = (cr * fr - ci * fi) + (ar * ir - ai * ii);
    const float ct_i = (cr * fi + ci * fr) + (ar * ii + ai * ir);

    const float tr = tanhf(ct_r);
    const float ti = tanhf(ct_i);
    const float ht_r = orr * tr - oi * ti;
    const float ht_i = orr * ti + oi * tr;

    const size_t hrow = (size_t)b * 2048;
    const size_t coff = (size_t)BDIM * 2048;
    out[hrow + o]               = ht_r;
    out[hrow + 1024 + o]        = ht_i;
    out[coff + hrow + o]        = ct_r;
    out[coff + hrow + 1024 + o] = ct_i;
}

extern "C" void kernel_launch(void* const* d_in, const int* in_sizes, int n_in,
                              void* d_out, int out_size)
{
    const float* input = (const float*)d_in[0];
    const float* h_x   = (const float*)d_in[1];
    const float* c_x   = (const float*)d_in[2];
    const float* Uw_r  = (const float*)d_in[3];
    const float* Uw_i  = (const float*)d_in[4];
    const float* Ub_r  = (const float*)d_in[5];
    const float* Ub_i  = (const float*)d_in[6];
    const float* Ww_r  = (const float*)d_in[7];
    const float* Ww_i  = (const float*)d_in[8];
    const float* Wb_r  = (const float*)d_in[9];
    const float* Wb_i  = (const float*)d_in[10];
    float* out = (float*)d_out;

    cudaFuncSetAttribute(clstm_tc_gemm_kernel,
                         cudaFuncAttributeMaxDynamicSharedMemorySize, SMEM_BYTES);

    prep_act_kernel<<<(BDIM * KTOT / 4) / 256, 256>>>(input, h_x);
    prep_w_kernel<<<(NTOT * KTOT / 4) / 256, 256>>>(Uw_r, Uw_i, Ww_r, Ww_i);

    dim3 grid(NTOT / 128, BDIM / 128);   // (64, 32)
    clstm_tc_gemm_kernel<<<grid, 256, SMEM_BYTES>>>();

    clstm_epilogue_kernel<<<(BDIM * HDIM) / 256, 256>>>(c_x, Ub_r, Ub_i, Wb_r, Wb_i, out);
}

// round 4
// speedup vs baseline: 8.4471x; 1.1312x over previous
#include <cuda_runtime.h>
#include <cuda_bf16.h>

// CLSTM cell, tensor-core GEMM:
//  - sm_103a pass: tcgen05 cta_group::2 bf16 SS MMA, 256x256 cluster tile, TMEM accum
//  - plain sm_103 pass: mma.sync m16n8k16 bf16 fallback (never runs on GB300)
// z = [xr|xi|hr|hi] @ Wcomb^T  (M=4096, N=8192, K=4096), fp32 via bf16 hi/lo 3-term.

#define BDIM 4096
#define HDIM 1024
#define KTOT 4096
#define NTOT 8192

// ---------------- static device scratch ----------------
__device__ __align__(256) __nv_bfloat16 g_Ah[(size_t)BDIM * KTOT];
__device__ __align__(256) __nv_bfloat16 g_Al[(size_t)BDIM * KTOT];
__device__ __align__(256) __nv_bfloat16 g_Bh[(size_t)NTOT * KTOT];
__device__ __align__(256) __nv_bfloat16 g_Bl[(size_t)NTOT * KTOT];
__device__ float g_z[(size_t)BDIM * NTOT];

// ---------------- common helpers ----------------
__device__ __forceinline__ unsigned smem_to_u32(const void* p) {
    unsigned a;
    asm("{ .reg .u64 t; cvta.to.shared.u64 t, %1; cvt.u32.u64 %0, t; }"
        : "=r"(a) : "l"(p));
    return a;
}
__device__ __forceinline__ void cp_async16(unsigned dst, const void* src) {
    asm volatile("cp.async.cg.shared.global [%0], [%1], 16;"
        :: "r"(dst), "l"(src) : "memory");
}
#define CP_COMMIT() asm volatile("cp.async.commit_group;" ::: "memory")
#define CP_WAIT1()  asm volatile("cp.async.wait_group 1;" ::: "memory")

#define SMEM_BYTES 133120

// ============================================================
//                     GEMM kernel
// ============================================================
__global__ __launch_bounds__(256, 1) __cluster_dims__(2, 1, 1)
void clstm_tc_gemm_kernel() {
    extern __shared__ char dsm[];

#ifdef __CUDA_ARCH_FEAT_SM103_ALL
    // ================= tcgen05 cg2 path (sm_103a) =================
    // Cluster of 2 CTAs computes a 256x256 tile. K-chunk 64, 2 stages.
    // Per-CTA stage = Ah16K|Al16K|Bh16K|Bl16K = 64KB.
    #define KCH 64
    #define NCHUNK (KTOT / KCH)
    #define STAGE_BYTES 65536
    #define A_H 0
    #define A_L 16384
    #define B_H 32768
    #define B_L 49152
    // idesc: dtype=F32, a/btype=BF16, N=128, M=256 (cg2)
    #define IDESC ((1u << 4) | (1u << 7) | (1u << 10) | (16u << 17) | (16u << 24))

    const unsigned base = smem_to_u32(dsm);
    const unsigned ctrl = base;
    const unsigned tiles = (base + 1024 + 1023) & ~1023u;

    const unsigned full0 = ctrl + 0,  full1 = ctrl + 8;
    const unsigned emp0  = ctrl + 16, emp1  = ctrl + 24;
    const unsigned done  = ctrl + 32;
    const unsigned xf0   = ctrl + 40, xf1   = ctrl + 48;
    const unsigned tptr  = ctrl + 64;

    const int tid = threadIdx.x;
    const int wid = tid >> 5;
    const unsigned rank = blockIdx.x & 1;           // cluster rank along x
    const unsigned m0 = blockIdx.y * 256;
    const unsigned n0 = (blockIdx.x >> 1) * 256;

    #define MBAR_INIT(a, c) \
        asm volatile("mbarrier.init.shared.b64 [%0], %1;" :: "r"(a), "r"((unsigned)(c)) : "memory")
    #define MBAR_WAIT(a, ph) do {                                                   \
        asm volatile("{\n\t.reg .pred P1;\n\t"                                      \
            "WL_%=:\n\t"                                                            \
            "mbarrier.try_wait.parity.acquire.cta.shared::cta.b64 P1, [%0], %1, 0x989680;\n\t" \
            "@P1 bra.uni WD_%=;\n\t"                                                \
            "bra.uni WL_%=;\n\t"                                                    \
            "WD_%=:\n\t}"                                                           \
            :: "r"(a), "r"((unsigned)(ph)) : "memory");                             \
    } while (0)
    #define MBAR_WAIT_CL(a, ph) do {                                                \
        asm volatile("{\n\t.reg .pred P1;\n\t"                                      \
            "WL_%=:\n\t"                                                            \
            "mbarrier.try_wait.parity.acquire.cluster.shared::cta.b64 P1, [%0], %1, 0x989680;\n\t" \
            "@P1 bra.uni WD_%=;\n\t"                                                \
            "bra.uni WL_%=;\n\t"                                                    \
            "WD_%=:\n\t}"                                                           \
            :: "r"(a), "r"((unsigned)(ph)) : "memory");                             \
    } while (0)
    #define CLUSTER_SYNC_() do {                                                    \
        asm volatile("barrier.cluster.arrive.aligned;" ::: "memory");               \
        asm volatile("barrier.cluster.wait.aligned;" ::: "memory");                 \
    } while (0)
    #define MMA_CG2(d, adesc, bdesc, en) \
        asm volatile("{\n\t.reg .pred p;\n\tsetp.ne.u32 p, %4, 0;\n\t"              \
            "tcgen05.mma.cta_group::2.kind::f16 [%0], %1, %2, %3, "                 \
            "{%5,%5,%5,%5,%5,%5,%5,%5}, p;\n\t}"                                    \
            :: "r"(d), "l"(adesc), "l"(bdesc), "r"(IDESC), "r"((unsigned)(en)),     \
               "r"(0u) : "memory")

    if (tid == 0) {
        MBAR_INIT(full0, 128); MBAR_INIT(full1, 128);
        MBAR_INIT(emp0, 1);    MBAR_INIT(emp1, 1);
        MBAR_INIT(done, 1);
        MBAR_INIT(xf0, 2);     MBAR_INIT(xf1, 2);
    }
    if (wid == 4)
        asm volatile("tcgen05.alloc.cta_group::2.sync.aligned.shared::cta.b32 [%0], %1;"
            :: "r"(tptr), "r"(256u) : "memory");
    __syncthreads();

    unsigned tmem;
    asm volatile("ld.shared.b32 %0, [%1];" : "=r"(tmem) : "r"(tptr));

    // All mbarriers + alloc visible cluster-wide before any cross-CTA signaling.
    CLUSTER_SYNC_();

    if (tid < 128) {
        // ---- loader warpgroup (both CTAs): 64KB/chunk into local smem ----
        for (int i = 0; i < NCHUNK; i++) {
            const int s = i & 1, w = i >> 1;
            const unsigned fullb = s ? full1 : full0;
            const unsigned empb  = s ? emp1  : emp0;
            if (w >= 1) MBAR_WAIT(empb, (w - 1) & 1);
            const unsigned sb = tiles + s * STAGE_BYTES;
            const unsigned k0 = i * KCH;
            // A: this CTA's 128 rows (m0 + rank*128 ..), hi+lo = 2048 x 16B
#pragma unroll
            for (int it = 0; it < 16; it++) {
                const unsigned t2 = (unsigned)tid + 128u * it;
                const unsigned hl = t2 >> 10, rem = t2 & 1023;
                const unsigned r = rem >> 3, u = rem & 7;
                const __nv_bfloat16* src = (hl ? g_Al : g_Ah)
                    + (size_t)(m0 + rank * 128 + r) * KTOT + k0 + u * 8;
                unsigned off = r * 128 + u * 16;
                off ^= (off >> 3) & 0x70;
                cp_async16(sb + A_H + hl * 16384 + off, src);
            }
            // B: 128 rows: half h (N-half), local 64 rows each.
            // smem row rB: half = rB>>6, global n = n0 + half*128 + rank*64 + (rB&63)
#pragma unroll
            for (int it = 0; it < 16; it++) {
                const unsigned t3 = (unsigned)tid + 128u * it;
                const unsigned hl = t3 >> 10, rem = t3 & 1023;
                const unsigned rB = rem >> 3, u = rem & 7;
                const unsigned gn = n0 + ((rB >> 6) << 7) + rank * 64 + (rB & 63);
                const __nv_bfloat16* src = (hl ? g_Bl : g_Bh)
                    + (size_t)gn * KTOT + k0 + u * 8;
                unsigned off = rB * 128 + u * 16;
                off ^= (off >> 3) & 0x70;
                cp_async16(sb + B_H + hl * 16384 + off, src);
            }
            asm volatile("cp.async.mbarrier.arrive.noinc.shared::cta.b64 [%0];"
                :: "r"(fullb) : "memory");
        }
    } else if (tid == 128) {
        // ---- MMA issue thread (leader CTA only) ----
        if (rank == 0) {
            const unsigned long long DBASE =
                (2ull << 61) | (1ull << 46) | (64ull << 32) | (1ull << 16);
            for (int i = 0; i < NCHUNK; i++) {
                const int s = i & 1, w = i >> 1;
                const unsigned xfb  = s ? xf1  : xf0;
                const unsigned empb = s ? emp1 : emp0;
                MBAR_WAIT_CL(xfb, w & 1);
                asm volatile("fence.proxy.async.shared::cta;" ::: "memory");
                const unsigned sb = tiles + s * STAGE_BYTES;
                const unsigned long long ah = DBASE | ((unsigned long long)((sb + A_H) >> 4) & 0x3FFF);
                const unsigned long long al = DBASE | ((unsigned long long)((sb + A_L) >> 4) & 0x3FFF);
                const unsigned long long bh = DBASE | ((unsigned long long)((sb + B_H) >> 4) & 0x3FFF);
                const unsigned long long bl = DBASE | ((unsigned long long)((sb + B_L) >> 4) & 0x3FFF);
#pragma unroll
                for (int half = 0; half < 2; half++) {
                    const unsigned d = tmem + half * 128;
                    const unsigned long long bo = (unsigned long long)half * 512; // 8KB
#pragma unroll
                    for (int ks = 0; ks < 4; ks++)
                        MMA_CG2(d, ah + ks * 2, bh + bo + ks * 2,
                                (i == 0 && ks == 0) ? 0u : 1u);
#pragma unroll
                    for (int ks = 0; ks < 4; ks++)
                        MMA_CG2(d, ah + ks * 2, bl + bo + ks * 2, 1u);
#pragma unroll
                    for (int ks = 0; ks < 4; ks++)
                        MMA_CG2(d, al + ks * 2, bh + bo + ks * 2, 1u);
                }
                asm volatile("tcgen05.commit.cta_group::2.mbarrier::arrive::one"
                    ".shared::cluster.multicast::cluster.b64 [%0], %1;"
                    :: "r"(empb), "h"((unsigned short)0x3) : "memory");
            }
            asm volatile("tcgen05.commit.cta_group::2.mbarrier::arrive::one"
                ".shared::cluster.multicast::cluster.b64 [%0], %1;"
                :: "r"(done), "h"((unsigned short)0x3) : "memory");
        }
        MBAR_WAIT(done, 0);
    } else if (tid == 160) {
        // ---- relay: local full -> leader's xfull (cluster release-arrive) ----
        for (int i = 0; i < NCHUNK; i++) {
            const int s = i & 1, w = i >> 1;
            const unsigned fullb = s ? full1 : full0;
            const unsigned xfb   = s ? xf1  : xf0;
            MBAR_WAIT(fullb, w & 1);
            asm volatile("fence.proxy.async.shared::cta;" ::: "memory");
            asm volatile("{\n\t.reg .b32 rem;\n\t"
                "mapa.shared::cluster.u32 rem, %0, 0;\n\t"
                "mbarrier.arrive.release.cluster.shared::cluster.b64 _, [rem];\n\t}"
                :: "r"(xfb) : "memory");
        }
    }
    __syncthreads();

    // ---- TMEM -> g_z (warps 0..3: this CTA's 128 rows x 256 cols fp32) ----
    if (tid < 128) {
        asm volatile("tcgen05.fence::after_thread_sync;" ::: "memory");
        const int lid = tid & 31;
        const unsigned woff = ((unsigned)(tid >> 5)) << 21;
        float* rowp = g_z
            + (size_t)(m0 + rank * 128 + (tid >> 5) * 32 + lid) * NTOT + n0;
#pragma unroll
        for (int j = 0; j < 8; j++) {
            unsigned r[32];
            asm volatile("tcgen05.ld.sync.aligned.32x32b.x32.b32 "
                "{%0, %1, %2, %3, %4, %5, %6, %7, "
                " %8, %9, %10, %11, %12, %13, %14, %15, "
                " %16, %17, %18, %19, %20, %21, %22, %23, "
                " %24, %25, %26, %27, %28, %29, %30, %31}, [%32];"
                : "=r"(r[0]),  "=r"(r[1]),  "=r"(r[2]),  "=r"(r[3]),
                  "=r"(r[4]),  "=r"(r[5]),  "=r"(r[6]),  "=r"(r[7]),
                  "=r"(r[8]),  "=r"(r[9]),  "=r"(r[10]), "=r"(r[11]),
                  "=r"(r[12]), "=r"(r[13]), "=r"(r[14]), "=r"(r[15]),
                  "=r"(r[16]), "=r"(r[17]), "=r"(r[18]), "=r"(r[19]),
                  "=r"(r[20]), "=r"(r[21]), "=r"(r[22]), "=r"(r[23]),
                  "=r"(r[24]), "=r"(r[25]), "=r"(r[26]), "=r"(r[27]),
                  "=r"(r[28]), "=r"(r[29]), "=r"(r[30]), "=r"(r[31])
                : "r"(tmem + woff + j * 32));
            asm volatile("tcgen05.wait::ld.sync.aligned;" ::: "memory");
#pragma unroll
            for (int c4 = 0; c4 < 8; c4++) {
                float4 v = make_float4(__uint_as_float(r[c4 * 4 + 0]),
                                       __uint_as_float(r[c4 * 4 + 1]),
                                       __uint_as_float(r[c4 * 4 + 2]),
                                       __uint_as_float(r[c4 * 4 + 3]));
                *reinterpret_cast<float4*>(rowp + j * 32 + c4 * 4) = v;
            }
        }
        asm volatile("tcgen05.fence::before_thread_sync;" ::: "memory");
    }
    __syncthreads();
    if (wid == 4) {
        asm volatile("tcgen05.relinquish_alloc_permit.cta_group::2.sync.aligned;");
        asm volatile("tcgen05.dealloc.cta_group::2.sync.aligned.b32 %0, %1;"
            :: "r"(tmem), "r"(256u));
    }
    CLUSTER_SYNC_();

#else
    // ================= HMMA fallback path (plain sm_103; never runs) =================
    #define HKC 32
    #define HNCH (KTOT / HKC)
    #define HSTG 40960
    #define HA_H 0
    #define HA_L 10240
    #define HB_H 20480
    #define HB_L 30720
    #define RST 80

    const int tid = threadIdx.x;
    const int lane = tid & 31;
    const int w = tid >> 5;
    const unsigned rank = blockIdx.x & 1;
    const unsigned m0 = blockIdx.y * 256 + rank * 128;
    const unsigned n0base = (blockIdx.x >> 1) * 256;
    const unsigned base = smem_to_u32(dsm);
    const unsigned m_base = (unsigned)(w & 1) * 64;
    const unsigned n_base = (unsigned)(w >> 1) * 32;

    #define LDSM_X4(r0, r1, r2, r3, addr) \
        asm volatile("ldmatrix.sync.aligned.m8n8.x4.shared.b16 {%0,%1,%2,%3}, [%4];" \
            : "=r"(r0), "=r"(r1), "=r"(r2), "=r"(r3) : "r"(addr))
    #define LDSM_X2(r0, r1, addr) \
        asm volatile("ldmatrix.sync.aligned.m8n8.x2.shared.b16 {%0,%1}, [%2];" \
            : "=r"(r0), "=r"(r1) : "r"(addr))
    #define MMA_BF16(ac, av, bv) \
        asm volatile("mma.sync.aligned.m16n8k16.row.col.f32.bf16.bf16.f32 " \
            "{%0,%1,%2,%3}, {%4,%5,%6,%7}, {%8,%9}, {%0,%1,%2,%3};" \
            : "+f"((ac)[0]), "+f"((ac)[1]), "+f"((ac)[2]), "+f"((ac)[3]) \
            : "r"((av)[0]), "r"((av)[1]), "r"((av)[2]), "r"((av)[3]), \
              "r"((bv)[0]), "r"((bv)[1]))

    for (int nh = 0; nh < 2; nh++) {
        const unsigned n0 = n0base + nh * 128;

        float acc[4][4][4];
#pragma unroll
        for (int a = 0; a < 4; a++)
#pragma unroll
            for (int b = 0; b < 4; b++)
#pragma unroll
                for (int c = 0; c < 4; c++) acc[a][b][c] = 0.0f;

        auto load_stage = [&](unsigned sb, unsigned k0) {
#pragma unroll
            for (int it = 0; it < 8; it++) {
                const unsigned idx = (unsigned)tid + 256u * it;
                const unsigned mat = idx >> 9;
                const unsigned rem = idx & 511;
                const unsigned row = rem >> 2;
                const unsigned c = rem & 3;
                const __nv_bfloat16* src;
                if (mat == 0)      src = g_Ah + (size_t)(m0 + row) * KTOT + k0 + c * 8;
                else if (mat == 1) src = g_Al + (size_t)(m0 + row) * KTOT + k0 + c * 8;
                else if (mat == 2) src = g_Bh + (size_t)(n0 + row) * KTOT + k0 + c * 8;
                else               src = g_Bl + (size_t)(n0 + row) * KTOT + k0 + c * 8;
                cp_async16(sb + mat * 10240 + row * RST + c * 16, src);
            }
        };

        load_stage(base + 0 * HSTG, 0);   CP_COMMIT();
        load_stage(base + 1 * HSTG, HKC); CP_COMMIT();

        for (int i = 0; i < HNCH; i++) {
            CP_WAIT1();
            __syncthreads();
            if (i + 2 < HNCH) load_stage(base + (unsigned)((i + 2) % 3) * HSTG, (i + 2) * HKC);
            CP_COMMIT();

            const unsigned sb = base + (unsigned)(i % 3) * HSTG;
#pragma unroll
            for (int ks = 0; ks < 2; ks++) {
                unsigned a[4][4], bhv[4][2], blv[4][2];
                const unsigned acol = (unsigned)(ks * 2 + (lane >> 4)) * 16;
                const unsigned bcol = (unsigned)(ks * 2 + ((lane >> 3) & 1)) * 16;
#pragma unroll
                for (int mt = 0; mt < 4; mt++) {
                    const unsigned ad = sb + HA_H
                        + (m_base + mt * 16 + (lane & 15)) * RST + acol;
                    LDSM_X4(a[mt][0], a[mt][1], a[mt][2], a[mt][3], ad);
                }
#pragma unroll
                for (int nt = 0; nt < 4; nt++) {
                    const unsigned brow = (n_base + nt * 8 + (lane & 7)) * RST + bcol;
                    LDSM_X2(bhv[nt][0], bhv[nt][1], sb + HB_H + brow);
                    LDSM_X2(blv[nt][0], blv[nt][1], sb + HB_L + brow);
                }
#pragma unroll
                for (int mt = 0; mt < 4; mt++)
#pragma unroll
                    for (int nt = 0; nt < 4; nt++) {
                        MMA_BF16(acc[mt][nt], a[mt], bhv[nt]);
                        MMA_BF16(acc[mt][nt], a[mt], blv[nt]);
                    }
#pragma unroll
                for (int mt = 0; mt < 4; mt++) {
                    const unsigned ad = sb + HA_L
                        + (m_base + mt * 16 + (lane & 15)) * RST + acol;
                    LDSM_X4(a[mt][0], a[mt][1], a[mt][2], a[mt][3], ad);
                }
#pragma unroll
                for (int mt = 0; mt < 4; mt++)
#pragma unroll
                    for (int nt = 0; nt < 4; nt++)
                        MMA_BF16(acc[mt][nt], a[mt], bhv[nt]);
            }
            __syncthreads();
        }

#pragma unroll
        for (int mt = 0; mt < 4; mt++) {
            const unsigned row0 = m0 + m_base + mt * 16 + (lane >> 2);
#pragma unroll
            for (int nt = 0; nt < 4; nt++) {
                const unsigned col = n0 + n_base + nt * 8 + 2 * (lane & 3);
                *reinterpret_cast<float2*>(&g_z[(size_t)row0 * NTOT + col]) =
                    make_float2(acc[mt][nt][0], acc[mt][nt][1]);
                *reinterpret_cast<float2*>(&g_z[(size_t)(row0 + 8) * NTOT + col]) =
                    make_float2(acc[mt][nt][2], acc[mt][nt][3]);
            }
        }
        __syncthreads();
    }
#endif
}

// ---------------- prep kernels ----------------
__device__ __forceinline__ void split_bf16(float v, __nv_bfloat16& hi, __nv_bfloat16& lo) {
    hi = __float2bfloat16_rn(v);
    lo = __float2bfloat16_rn(v - __bfloat162float(hi));
}

__global__ __launch_bounds__(256)
void prep_act_kernel(const float* __restrict__ input, const float* __restrict__ h_x) {
    const unsigned idx = blockIdx.x * 256 + threadIdx.x;
    const unsigned m = idx >> 10;
    const unsigned k = (idx & 1023) * 4;
    const float* src = (k < 2048) ? (input + (size_t)m * 2048 + k)
                                  : (h_x   + (size_t)m * 2048 + (k - 2048));
    float4 v = *reinterpret_cast<const float4*>(src);
    union { __nv_bfloat16 b[4]; uint2 u; } ph, pl;
    split_bf16(v.x, ph.b[0], pl.b[0]);
    split_bf16(v.y, ph.b[1], pl.b[1]);
    split_bf16(v.z, ph.b[2], pl.b[2]);
    split_bf16(v.w, ph.b[3], pl.b[3]);
    const size_t off = (size_t)m * KTOT + k;
    *reinterpret_cast<uint2*>(&g_Ah[off]) = ph.u;
    *reinterpret_cast<uint2*>(&g_Al[off]) = pl.u;
}

__global__ __launch_bounds__(256)
void prep_w_kernel(const float* __restrict__ Uw_r, const float* __restrict__ Uw_i,
                   const float* __restrict__ Ww_r, const float* __restrict__ Ww_i) {
    const unsigned idx = blockIdx.x * 256 + threadIdx.x;
    const unsigned n = idx >> 10;
    const unsigned k = (idx & 1023) * 4;
    const unsigned ri = n >> 12, g = (n >> 10) & 3, o = n & 1023;
    const unsigned seg = k >> 10, kk = k & 1023;

    const float* src;
    float s;
    if (ri == 0) {
        switch (seg) {
            case 0: src = Uw_r; s =  1.0f; break;
            case 1: src = Uw_i; s = -1.0f; break;
            case 2: src = Ww_r; s =  1.0f; break;
            default: src = Ww_i; s = -1.0f; break;
        }
    } else {
        switch (seg) {
            case 0: src = Uw_i; s = 1.0f; break;
            case 1: src = Uw_r; s = 1.0f; break;
            case 2: src = Ww_i; s = 1.0f; break;
            default: src = Ww_r; s = 1.0f; break;
        }
    }
    float4 v = *reinterpret_cast<const float4*>(src + ((size_t)(g * 1024 + o)) * 1024 + kk);
    union { __nv_bfloat16 b[4]; uint2 u; } ph, pl;
    split_bf16(s * v.x, ph.b[0], pl.b[0]);
    split_bf16(s * v.y, ph.b[1], pl.b[1]);
    split_bf16(s * v.z, ph.b[2], pl.b[2]);
    split_bf16(s * v.w, ph.b[3], pl.b[3]);
    const size_t off = (size_t)n * KTOT + k;
    *reinterpret_cast<uint2*>(&g_Bh[off]) = ph.u;
    *reinterpret_cast<uint2*>(&g_Bl[off]) = pl.u;
}

// ---------------- pointwise epilogue ----------------
__device__ __forceinline__ float sigmoidf_(float x) {
    return 1.0f / (1.0f + expf(-x));
}

__global__ __launch_bounds__(256)
void clstm_epilogue_kernel(const float* __restrict__ c_x,
                           const float* __restrict__ Ub_r,
                           const float* __restrict__ Ub_i,
                           const float* __restrict__ Wb_r,
                           const float* __restrict__ Wb_i,
                           float* __restrict__ out)
{
    const int idx = blockIdx.x * blockDim.x + threadIdx.x;
    const int b = idx >> 10;
    const int o = idx & 1023;

    const float* z = g_z + (size_t)b * NTOT;

    float zr[4], zi[4];
#pragma unroll
    for (int gg = 0; gg < 4; gg++) {
        const int go = gg * 1024 + o;
        zr[gg] = z[go]        + Ub_r[go] + Wb_r[go];
        zi[gg] = z[4096 + go] + Ub_i[go] + Wb_i[go];
    }

    const float fr = sigmoidf_(zr[0]), fi = sigmoidf_(zi[0]);
    const float ir = sigmoidf_(zr[1]), ii = sigmoidf_(zi[1]);
    const float ar = tanhf(zr[2]),     ai = tanhf(zi[2]);
    const float orr = sigmoidf_(zr[3]), oi = sigmoidf_(zi[3]);

    const float cr = c_x[(size_t)b * 2048 + o];
    const float ci = c_x[(size_t)b * 2048 + 1024 + o];

    const float ct_r = (cr * fr - ci * fi) + (ar * ir - ai * ii);
    const float ct_i = (cr * fi + ci * fr) + (ar * ii + ai * ir);

    const float tr = tanhf(ct_r);
    const float ti = tanhf(ct_i);
    const float ht_r = orr * tr - oi * ti;
    const float ht_i = orr * ti + oi * tr;

    const size_t hrow = (size_t)b * 2048;
    const size_t coff = (size_t)BDIM * 2048;
    out[hrow + o]               = ht_r;
    out[hrow + 1024 + o]        = ht_i;
    out[coff + hrow + o]        = ct_r;
    out[coff + hrow + 1024 + o] = ct_i;
}

extern "C" void kernel_launch(void* const* d_in, const int* in_sizes, int n_in,
                              void* d_out, int out_size)
{
    const float* input = (const float*)d_in[0];
    const float* h_x   = (const float*)d_in[1];
    const float* c_x   = (const float*)d_in[2];
    const float* Uw_r  = (const float*)d_in[3];
    const float* Uw_i  = (const float*)d_in[4];
    const float* Ub_r  = (const float*)d_in[5];
    const float* Ub_i  = (const float*)d_in[6];
    const float* Ww_r  = (const float*)d_in[7];
    const float* Ww_i  = (const float*)d_in[8];
    const float* Wb_r  = (const float*)d_in[9];
    const float* Wb_i  = (const float*)d_in[10];
    float* out = (float*)d_out;

    cudaFuncSetAttribute(clstm_tc_gemm_kernel,
                         cudaFuncAttributeMaxDynamicSharedMemorySize, SMEM_BYTES);

    prep_act_kernel<<<(BDIM * KTOT / 4) / 256, 256>>>(input, h_x);
    prep_w_kernel<<<(NTOT * KTOT / 4) / 256, 256>>>(Uw_r, Uw_i, Ww_r, Ww_i);

    // clusters of 2 along x: cluster tile 256(M) x 256(N)
    dim3 grid((NTOT / 256) * 2, BDIM / 256);   // (64, 16) = 1024 CTAs
    clstm_tc_gemm_kernel<<<grid, 256, SMEM_BYTES>>>();

    clstm_epilogue_kernel<<<(BDIM * HDIM) / 256, 256>>>(c_x, Ub_r, Ub_i, Wb_r, Wb_i, out);
}

// round 5
// speedup vs baseline: 10.5062x; 1.2438x over previous
#include <cuda_runtime.h>
#include <cuda_bf16.h>

// CLSTM cell, tensor-core GEMM:
//  - sm_103a pass: tcgen05 cta_group::2 bf16 SS MMA, 256x256 cluster tile,
//    3-stage cp.async pipeline, TMEM accum
//  - plain sm_103 pass: mma.sync m16n8k16 bf16 fallback (never runs on GB300)
// z = [xr|xi|hr|hi] @ Wcomb^T  (M=4096, N=8192, K=4096), fp32 via bf16 hi/lo 3-term.

#define BDIM 4096
#define HDIM 1024
#define KTOT 4096
#define NTOT 8192

// ---------------- static device scratch ----------------
__device__ __align__(256) __nv_bfloat16 g_Ah[(size_t)BDIM * KTOT];
__device__ __align__(256) __nv_bfloat16 g_Al[(size_t)BDIM * KTOT];
__device__ __align__(256) __nv_bfloat16 g_Bh[(size_t)NTOT * KTOT];
__device__ __align__(256) __nv_bfloat16 g_Bl[(size_t)NTOT * KTOT];
__device__ float g_z[(size_t)BDIM * NTOT];

// ---------------- common helpers ----------------
__device__ __forceinline__ unsigned smem_to_u32(const void* p) {
    unsigned a;
    asm("{ .reg .u64 t; cvta.to.shared.u64 t, %1; cvt.u32.u64 %0, t; }"
        : "=r"(a) : "l"(p));
    return a;
}
__device__ __forceinline__ void cp_async16(unsigned dst, const void* src) {
    asm volatile("cp.async.cg.shared.global [%0], [%1], 16;"
        :: "r"(dst), "l"(src) : "memory");
}
#define CP_COMMIT() asm volatile("cp.async.commit_group;" ::: "memory")
#define CP_WAIT1()  asm volatile("cp.async.wait_group 1;" ::: "memory")

#define NSTAGE 3
#define SMEM_BYTES (1024 + NSTAGE * 65536 + 1024)

// ============================================================
//                     GEMM kernel
// ============================================================
__global__ __launch_bounds__(256, 1) __cluster_dims__(2, 1, 1)
void clstm_tc_gemm_kernel() {
    extern __shared__ char dsm[];

#ifdef __CUDA_ARCH_FEAT_SM103_ALL
    // ================= tcgen05 cg2 path (sm_103a) =================
    #define KCH 64
    #define NCHUNK (KTOT / KCH)
    #define STAGE_BYTES 65536
    #define A_H 0
    #define A_L 16384
    #define B_H 32768
    #define B_L 49152
    // idesc: dtype=F32, a/btype=BF16, N=128, M=256 (cg2)
    #define IDESC ((1u << 4) | (1u << 7) | (1u << 10) | (16u << 17) | (16u << 24))

    const unsigned base = smem_to_u32(dsm);
    const unsigned ctrl = base;
    const unsigned tiles = (base + 1024 + 1023) & ~1023u;

    // barrier slots: full[3] @0,8,16; emp[3] @24,32,40; xf[3] @48,56,64; done @72; tptr @80
    const unsigned fullB = ctrl + 0;
    const unsigned empB  = ctrl + 24;
    const unsigned xfB   = ctrl + 48;
    const unsigned done  = ctrl + 72;
    const unsigned tptr  = ctrl + 80;

    const int tid = threadIdx.x;
    const int wid = tid >> 5;
    const unsigned rank = blockIdx.x & 1;
    const unsigned m0 = blockIdx.y * 256;
    const unsigned n0 = (blockIdx.x >> 1) * 256;

    #define MBAR_INIT(a, c) \
        asm volatile("mbarrier.init.shared.b64 [%0], %1;" :: "r"(a), "r"((unsigned)(c)) : "memory")
    #define MBAR_WAIT(a, ph) do {                                                   \
        asm volatile("{\n\t.reg .pred P1;\n\t"                                      \
            "WL_%=:\n\t"                                                            \
            "mbarrier.try_wait.parity.acquire.cta.shared::cta.b64 P1, [%0], %1, 0x989680;\n\t" \
            "@P1 bra.uni WD_%=;\n\t"                                                \
            "bra.uni WL_%=;\n\t"                                                    \
            "WD_%=:\n\t}"                                                           \
            :: "r"(a), "r"((unsigned)(ph)) : "memory");                             \
    } while (0)
    #define MBAR_WAIT_CL(a, ph) do {                                                \
        asm volatile("{\n\t.reg .pred P1;\n\t"                                      \
            "WL_%=:\n\t"                                                            \
            "mbarrier.try_wait.parity.acquire.cluster.shared::cta.b64 P1, [%0], %1, 0x989680;\n\t" \
            "@P1 bra.uni WD_%=;\n\t"                                                \
            "bra.uni WL_%=;\n\t"                                                    \
            "WD_%=:\n\t}"                                                           \
            :: "r"(a), "r"((unsigned)(ph)) : "memory");                             \
    } while (0)
    #define CLUSTER_SYNC_() do {                                                    \
        asm volatile("barrier.cluster.arrive.aligned;" ::: "memory");               \
        asm volatile("barrier.cluster.wait.aligned;" ::: "memory");                 \
    } while (0)
    #define MMA_CG2(d, adesc, bdesc, en) \
        asm volatile("{\n\t.reg .pred p;\n\tsetp.ne.u32 p, %4, 0;\n\t"              \
            "tcgen05.mma.cta_group::2.kind::f16 [%0], %1, %2, %3, "                 \
            "{%5,%5,%5,%5,%5,%5,%5,%5}, p;\n\t}"                                    \
            :: "r"(d), "l"(adesc), "l"(bdesc), "r"(IDESC), "r"((unsigned)(en)),     \
               "r"(0u) : "memory")

    if (tid == 0) {
#pragma unroll
        for (int s = 0; s < NSTAGE; s++) {
            MBAR_INIT(fullB + s * 8, 128);
            MBAR_INIT(empB  + s * 8, 1);
            MBAR_INIT(xfB   + s * 8, 2);
        }
        MBAR_INIT(done, 1);
    }
    if (wid == 4)
        asm volatile("tcgen05.alloc.cta_group::2.sync.aligned.shared::cta.b32 [%0], %1;"
            :: "r"(tptr), "r"(256u) : "memory");
    __syncthreads();

    unsigned tmem;
    asm volatile("ld.shared.b32 %0, [%1];" : "=r"(tmem) : "r"(tptr));

    CLUSTER_SYNC_();

    if (tid < 128) {
        // ---- loader warpgroup (both CTAs): 64KB/chunk into local smem ----
        for (int i = 0; i < NCHUNK; i++) {
            const int s = i % NSTAGE, w = i / NSTAGE;
            const unsigned fullb = fullB + s * 8;
            const unsigned empb  = empB  + s * 8;
            if (w >= 1) MBAR_WAIT(empb, (w - 1) & 1);
            const unsigned sb = tiles + s * STAGE_BYTES;
            const unsigned k0 = i * KCH;
#pragma unroll
            for (int it = 0; it < 16; it++) {   // A hi+lo: 2048 x 16B
                const unsigned t2 = (unsigned)tid + 128u * it;
                const unsigned hl = t2 >> 10, rem = t2 & 1023;
                const unsigned r = rem >> 3, u = rem & 7;
                const __nv_bfloat16* src = (hl ? g_Al : g_Ah)
                    + (size_t)(m0 + rank * 128 + r) * KTOT + k0 + u * 8;
                unsigned off = r * 128 + u * 16;
                off ^= (off >> 3) & 0x70;
                cp_async16(sb + A_H + hl * 16384 + off, src);
            }
#pragma unroll
            for (int it = 0; it < 16; it++) {   // B hi+lo: 2048 x 16B (cg2 split)
                const unsigned t3 = (unsigned)tid + 128u * it;
                const unsigned hl = t3 >> 10, rem = t3 & 1023;
                const unsigned rB = rem >> 3, u = rem & 7;
                const unsigned gn = n0 + ((rB >> 6) << 7) + rank * 64 + (rB & 63);
                const __nv_bfloat16* src = (hl ? g_Bl : g_Bh)
                    + (size_t)gn * KTOT + k0 + u * 8;
                unsigned off = rB * 128 + u * 16;
                off ^= (off >> 3) & 0x70;
                cp_async16(sb + B_H + hl * 16384 + off, src);
            }
            asm volatile("cp.async.mbarrier.arrive.noinc.shared::cta.b64 [%0];"
                :: "r"(fullb) : "memory");
        }
    } else if (tid == 128) {
        // ---- MMA issue thread (leader CTA only) ----
        if (rank == 0) {
            const unsigned long long DBASE =
                (2ull << 61) | (1ull << 46) | (64ull << 32) | (1ull << 16);
            for (int i = 0; i < NCHUNK; i++) {
                const int s = i % NSTAGE, w = i / NSTAGE;
                const unsigned xfb  = xfB  + s * 8;
                const unsigned empb = empB + s * 8;
                MBAR_WAIT_CL(xfb, w & 1);
                asm volatile("fence.proxy.async.shared::cta;" ::: "memory");
                const unsigned sb = tiles + s * STAGE_BYTES;
                const unsigned long long ah = DBASE | ((unsigned long long)((sb + A_H) >> 4) & 0x3FFF);
                const unsigned long long al = DBASE | ((unsigned long long)((sb + A_L) >> 4) & 0x3FFF);
                const unsigned long long bh = DBASE | ((unsigned long long)((sb + B_H) >> 4) & 0x3FFF);
                const unsigned long long bl = DBASE | ((unsigned long long)((sb + B_L) >> 4) & 0x3FFF);
#pragma unroll
                for (int half = 0; half < 2; half++) {
                    const unsigned d = tmem + half * 128;
                    const unsigned long long bo = (unsigned long long)half * 512;
#pragma unroll
                    for (int ks = 0; ks < 4; ks++)
                        MMA_CG2(d, ah + ks * 2, bh + bo + ks * 2,
                                (i == 0 && ks == 0) ? 0u : 1u);
#pragma unroll
                    for (int ks = 0; ks < 4; ks++)
                        MMA_CG2(d, ah + ks * 2, bl + bo + ks * 2, 1u);
#pragma unroll
                    for (int ks = 0; ks < 4; ks++)
                        MMA_CG2(d, al + ks * 2, bh + bo + ks * 2, 1u);
                }
                asm volatile("tcgen05.commit.cta_group::2.mbarrier::arrive::one"
                    ".shared::cluster.multicast::cluster.b64 [%0], %1;"
                    :: "r"(empb), "h"((unsigned short)0x3) : "memory");
            }
            asm volatile("tcgen05.commit.cta_group::2.mbarrier::arrive::one"
                ".shared::cluster.multicast::cluster.b64 [%0], %1;"
                :: "r"(done), "h"((unsigned short)0x3) : "memory");
        }
        MBAR_WAIT(done, 0);
    } else if (tid == 160) {
        // ---- relay: local full -> leader's xfull (cluster release-arrive) ----
        for (int i = 0; i < NCHUNK; i++) {
            const int s = i % NSTAGE, w = i / NSTAGE;
            const unsigned fullb = fullB + s * 8;
            const unsigned xfb   = xfB   + s * 8;
            MBAR_WAIT(fullb, w & 1);
            asm volatile("fence.proxy.async.shared::cta;" ::: "memory");
            asm volatile("{\n\t.reg .b32 rem;\n\t"
                "mapa.shared::cluster.u32 rem, %0, 0;\n\t"
                "mbarrier.arrive.release.cluster.shared::cluster.b64 _, [rem];\n\t}"
                :: "r"(xfb) : "memory");
        }
    }
    __syncthreads();

    // ---- TMEM -> g_z (warps 0..3: this CTA's 128 rows x 256 cols fp32) ----
    if (tid < 128) {
        asm volatile("tcgen05.fence::after_thread_sync;" ::: "memory");
        const int lid = tid & 31;
        const unsigned woff = ((unsigned)(tid >> 5)) << 21;
        float* rowp = g_z
            + (size_t)(m0 + rank * 128 + (tid >> 5) * 32 + lid) * NTOT + n0;
#pragma unroll
        for (int j = 0; j < 8; j++) {
            unsigned r[32];
            asm volatile("tcgen05.ld.sync.aligned.32x32b.x32.b32 "
                "{%0, %1, %2, %3, %4, %5, %6, %7, "
                " %8, %9, %10, %11, %12, %13, %14, %15, "
                " %16, %17, %18, %19, %20, %21, %22, %23, "
                " %24, %25, %26, %27, %28, %29, %30, %31}, [%32];"
                : "=r"(r[0]),  "=r"(r[1]),  "=r"(r[2]),  "=r"(r[3]),
                  "=r"(r[4]),  "=r"(r[5]),  "=r"(r[6]),  "=r"(r[7]),
                  "=r"(r[8]),  "=r"(r[9]),  "=r"(r[10]), "=r"(r[11]),
                  "=r"(r[12]), "=r"(r[13]), "=r"(r[14]), "=r"(r[15]),
                  "=r"(r[16]), "=r"(r[17]), "=r"(r[18]), "=r"(r[19]),
                  "=r"(r[20]), "=r"(r[21]), "=r"(r[22]), "=r"(r[23]),
                  "=r"(r[24]), "=r"(r[25]), "=r"(r[26]), "=r"(r[27]),
                  "=r"(r[28]), "=r"(r[29]), "=r"(r[30]), "=r"(r[31])
                : "r"(tmem + woff + j * 32));
            asm volatile("tcgen05.wait::ld.sync.aligned;" ::: "memory");
#pragma unroll
            for (int c4 = 0; c4 < 8; c4++) {
                float4 v = make_float4(__uint_as_float(r[c4 * 4 + 0]),
                                       __uint_as_float(r[c4 * 4 + 1]),
                                       __uint_as_float(r[c4 * 4 + 2]),
                                       __uint_as_float(r[c4 * 4 + 3]));
                *reinterpret_cast<float4*>(rowp + j * 32 + c4 * 4) = v;
            }
        }
        asm volatile("tcgen05.fence::before_thread_sync;" ::: "memory");
    }
    __syncthreads();
    if (wid == 4) {
        asm volatile("tcgen05.relinquish_alloc_permit.cta_group::2.sync.aligned;");
        asm volatile("tcgen05.dealloc.cta_group::2.sync.aligned.b32 %0, %1;"
            :: "r"(tmem), "r"(256u));
    }
    CLUSTER_SYNC_();

#else
    // ================= HMMA fallback path (plain sm_103; never runs) =================
    #define HKC 32
    #define HNCH (KTOT / HKC)
    #define HSTG 40960
    #define HA_H 0
    #define HA_L 10240
    #define HB_H 20480
    #define HB_L 30720
    #define RST 80

    const int tid = threadIdx.x;
    const int lane = tid & 31;
    const int w = tid >> 5;
    const unsigned rank = blockIdx.x & 1;
    const unsigned m0 = blockIdx.y * 256 + rank * 128;
    const unsigned n0base = (blockIdx.x >> 1) * 256;
    const unsigned base = smem_to_u32(dsm);
    const unsigned m_base = (unsigned)(w & 1) * 64;
    const unsigned n_base = (unsigned)(w >> 1) * 32;

    #define LDSM_X4(r0, r1, r2, r3, addr) \
        asm volatile("ldmatrix.sync.aligned.m8n8.x4.shared.b16 {%0,%1,%2,%3}, [%4];" \
            : "=r"(r0), "=r"(r1), "=r"(r2), "=r"(r3) : "r"(addr))
    #define LDSM_X2(r0, r1, addr) \
        asm volatile("ldmatrix.sync.aligned.m8n8.x2.shared.b16 {%0,%1}, [%2];" \
            : "=r"(r0), "=r"(r1) : "r"(addr))
    #define MMA_BF16(ac, av, bv) \
        asm volatile("mma.sync.aligned.m16n8k16.row.col.f32.bf16.bf16.f32 " \
            "{%0,%1,%2,%3}, {%4,%5,%6,%7}, {%8,%9}, {%0,%1,%2,%3};" \
            : "+f"((ac)[0]), "+f"((ac)[1]), "+f"((ac)[2]), "+f"((ac)[3]) \
            : "r"((av)[0]), "r"((av)[1]), "r"((av)[2]), "r"((av)[3]), \
              "r"((bv)[0]), "r"((bv)[1]))

    for (int nh = 0; nh < 2; nh++) {
        const unsigned n0 = n0base + nh * 128;

        float acc[4][4][4];
#pragma unroll
        for (int a = 0; a < 4; a++)
#pragma unroll
            for (int b = 0; b < 4; b++)
#pragma unroll
                for (int c = 0; c < 4; c++) acc[a][b][c] = 0.0f;

        auto load_stage = [&](unsigned sb, unsigned k0) {
#pragma unroll
            for (int it = 0; it < 8; it++) {
                const unsigned idx = (unsigned)tid + 256u * it;
                const unsigned mat = idx >> 9;
                const unsigned rem = idx & 511;
                const unsigned row = rem >> 2;
                const unsigned c = rem & 3;
                const __nv_bfloat16* src;
                if (mat == 0)      src = g_Ah + (size_t)(m0 + row) * KTOT + k0 + c * 8;
                else if (mat == 1) src = g_Al + (size_t)(m0 + row) * KTOT + k0 + c * 8;
                else if (mat == 2) src = g_Bh + (size_t)(n0 + row) * KTOT + k0 + c * 8;
                else               src = g_Bl + (size_t)(n0 + row) * KTOT + k0 + c * 8;
                cp_async16(sb + mat * 10240 + row * RST + c * 16, src);
            }
        };

        load_stage(base + 0 * HSTG, 0);   CP_COMMIT();
        load_stage(base + 1 * HSTG, HKC); CP_COMMIT();

        for (int i = 0; i < HNCH; i++) {
            CP_WAIT1();
            __syncthreads();
            if (i + 2 < HNCH) load_stage(base + (unsigned)((i + 2) % 3) * HSTG, (i + 2) * HKC);
            CP_COMMIT();

            const unsigned sb = base + (unsigned)(i % 3) * HSTG;
#pragma unroll
            for (int ks = 0; ks < 2; ks++) {
                unsigned a[4][4], bhv[4][2], blv[4][2];
                const unsigned acol = (unsigned)(ks * 2 + (lane >> 4)) * 16;
                const unsigned bcol = (unsigned)(ks * 2 + ((lane >> 3) & 1)) * 16;
#pragma unroll
                for (int mt = 0; mt < 4; mt++) {
                    const unsigned ad = sb + HA_H
                        + (m_base + mt * 16 + (lane & 15)) * RST + acol;
                    LDSM_X4(a[mt][0], a[mt][1], a[mt][2], a[mt][3], ad);
                }
#pragma unroll
                for (int nt = 0; nt < 4; nt++) {
                    const unsigned brow = (n_base + nt * 8 + (lane & 7)) * RST + bcol;
                    LDSM_X2(bhv[nt][0], bhv[nt][1], sb + HB_H + brow);
                    LDSM_X2(blv[nt][0], blv[nt][1], sb + HB_L + brow);
                }
#pragma unroll
                for (int mt = 0; mt < 4; mt++)
#pragma unroll
                    for (int nt = 0; nt < 4; nt++) {
                        MMA_BF16(acc[mt][nt], a[mt], bhv[nt]);
                        MMA_BF16(acc[mt][nt], a[mt], blv[nt]);
                    }
#pragma unroll
                for (int mt = 0; mt < 4; mt++) {
                    const unsigned ad = sb + HA_L
                        + (m_base + mt * 16 + (lane & 15)) * RST + acol;
                    LDSM_X4(a[mt][0], a[mt][1], a[mt][2], a[mt][3], ad);
                }
#pragma unroll
                for (int mt = 0; mt < 4; mt++)
#pragma unroll
                    for (int nt = 0; nt < 4; nt++)
                        MMA_BF16(acc[mt][nt], a[mt], bhv[nt]);
            }
            __syncthreads();
        }

#pragma unroll
        for (int mt = 0; mt < 4; mt++) {
            const unsigned row0 = m0 + m_base + mt * 16 + (lane >> 2);
#pragma unroll
            for (int nt = 0; nt < 4; nt++) {
                const unsigned col = n0 + n_base + nt * 8 + 2 * (lane & 3);
                *reinterpret_cast<float2*>(&g_z[(size_t)row0 * NTOT + col]) =
                    make_float2(acc[mt][nt][0], acc[mt][nt][1]);
                *reinterpret_cast<float2*>(&g_z[(size_t)(row0 + 8) * NTOT + col]) =
                    make_float2(acc[mt][nt][2], acc[mt][nt][3]);
            }
        }
        __syncthreads();
    }
#endif
}

// ---------------- prep kernels ----------------
__device__ __forceinline__ void split_bf16(float v, __nv_bfloat16& hi, __nv_bfloat16& lo) {
    hi = __float2bfloat16_rn(v);
    lo = __float2bfloat16_rn(v - __bfloat162float(hi));
}

__global__ __launch_bounds__(256)
void prep_act_kernel(const float* __restrict__ input, const float* __restrict__ h_x) {
    const unsigned idx = blockIdx.x * 256 + threadIdx.x;
    const unsigned m = idx >> 10;
    const unsigned k = (idx & 1023) * 4;
    const float* src = (k < 2048) ? (input + (size_t)m * 2048 + k)
                                  : (h_x   + (size_t)m * 2048 + (k - 2048));
    float4 v = *reinterpret_cast<const float4*>(src);
    union { __nv_bfloat16 b[4]; uint2 u; } ph, pl;
    split_bf16(v.x, ph.b[0], pl.b[0]);
    split_bf16(v.y, ph.b[1], pl.b[1]);
    split_bf16(v.z, ph.b[2], pl.b[2]);
    split_bf16(v.w, ph.b[3], pl.b[3]);
    const size_t off = (size_t)m * KTOT + k;
    *reinterpret_cast<uint2*>(&g_Ah[off]) = ph.u;
    *reinterpret_cast<uint2*>(&g_Al[off]) = pl.u;
}

__global__ __launch_bounds__(256)
void prep_w_kernel(const float* __restrict__ Uw_r, const float* __restrict__ Uw_i,
                   const float* __restrict__ Ww_r, const float* __restrict__ Ww_i) {
    const unsigned idx = blockIdx.x * 256 + threadIdx.x;
    const unsigned n = idx >> 10;
    const unsigned k = (idx & 1023) * 4;
    const unsigned ri = n >> 12, g = (n >> 10) & 3, o = n & 1023;
    const unsigned seg = k >> 10, kk = k & 1023;

    const float* src;
    float s;
    if (ri == 0) {
        switch (seg) {
            case 0: src = Uw_r; s =  1.0f; break;
            case 1: src = Uw_i; s = -1.0f; break;
            case 2: src = Ww_r; s =  1.0f; break;
            default: src = Ww_i; s = -1.0f; break;
        }
    } else {
        switch (seg) {
            case 0: src = Uw_i; s = 1.0f; break;
            case 1: src = Uw_r; s = 1.0f; break;
            case 2: src = Ww_i; s = 1.0f; break;
            default: src = Ww_r; s = 1.0f; break;
        }
    }
    float4 v = *reinterpret_cast<const float4*>(src + ((size_t)(g * 1024 + o)) * 1024 + kk);
    union { __nv_bfloat16 b[4]; uint2 u; } ph, pl;
    split_bf16(s * v.x, ph.b[0], pl.b[0]);
    split_bf16(s * v.y, ph.b[1], pl.b[1]);
    split_bf16(s * v.z, ph.b[2], pl.b[2]);
    split_bf16(s * v.w, ph.b[3], pl.b[3]);
    const size_t off = (size_t)n * KTOT + k;
    *reinterpret_cast<uint2*>(&g_Bh[off]) = ph.u;
    *reinterpret_cast<uint2*>(&g_Bl[off]) = pl.u;
}

// ---------------- pointwise epilogue ----------------
__device__ __forceinline__ float sigmoidf_(float x) {
    return 1.0f / (1.0f + expf(-x));
}

__global__ __launch_bounds__(256)
void clstm_epilogue_kernel(const float* __restrict__ c_x,
                           const float* __restrict__ Ub_r,
                           const float* __restrict__ Ub_i,
                           const float* __restrict__ Wb_r,
                           const float* __restrict__ Wb_i,
                           float* __restrict__ out)
{
    const int idx = blockIdx.x * blockDim.x + threadIdx.x;
    const int b = idx >> 10;
    const int o = idx & 1023;

    const float* z = g_z + (size_t)b * NTOT;

    float zr[4], zi[4];
#pragma unroll
    for (int gg = 0; gg < 4; gg++) {
        const int go = gg * 1024 + o;
        zr[gg] = z[go]        + Ub_r[go] + Wb_r[go];
        zi[gg] = z[4096 + go] + Ub_i[go] + Wb_i[go];
    }

    const float fr = sigmoidf_(zr[0]), fi = sigmoidf_(zi[0]);
    const float ir = sigmoidf_(zr[1]), ii = sigmoidf_(zi[1]);
    const float ar = tanhf(zr[2]),     ai = tanhf(zi[2]);
    const float orr = sigmoidf_(zr[3]), oi = sigmoidf_(zi[3]);

    const float cr = c_x[(size_t)b * 2048 + o];
    const float ci = c_x[(size_t)b * 2048 + 1024 + o];

    const float ct_r = (cr * fr - ci * fi) + (ar * ir - ai * ii);
    const float ct_i = (cr * fi + ci * fr) + (ar * ii + ai * ir);

    const float tr = tanhf(ct_r);
    const float ti = tanhf(ct_i);
    const float ht_r = orr * tr - oi * ti;
    const float ht_i = orr * ti + oi * tr;

    const size_t hrow = (size_t)b * 2048;
    const size_t coff = (size_t)BDIM * 2048;
    out[hrow + o]               = ht_r;
    out[hrow + 1024 + o]        = ht_i;
    out[coff + hrow + o]        = ct_r;
    out[coff + hrow + 1024 + o] = ct_i;
}

extern "C" void kernel_launch(void* const* d_in, const int* in_sizes, int n_in,
                              void* d_out, int out_size)
{
    const float* input = (const float*)d_in[0];
    const float* h_x   = (const float*)d_in[1];
    const float* c_x   = (const float*)d_in[2];
    const float* Uw_r  = (const float*)d_in[3];
    const float* Uw_i  = (const float*)d_in[4];
    const float* Ub_r  = (const float*)d_in[5];
    const float* Ub_i  = (const float*)d_in[6];
    const float* Ww_r  = (const float*)d_in[7];
    const float* Ww_i  = (const float*)d_in[8];
    const float* Wb_r  = (const float*)d_in[9];
    const float* Wb_i  = (const float*)d_in[10];
    float* out = (float*)d_out;

    cudaFuncSetAttribute(clstm_tc_gemm_kernel,
                         cudaFuncAttributeMaxDynamicSharedMemorySize, SMEM_BYTES);

    prep_act_kernel<<<(BDIM * KTOT / 4) / 256, 256>>>(input, h_x);
    prep_w_kernel<<<(NTOT * KTOT / 4) / 256, 256>>>(Uw_r, Uw_i, Ww_r, Ww_i);

    // clusters of 2 along x: cluster tile 256(M) x 256(N)
    dim3 grid((NTOT / 256) * 2, BDIM / 256);   // (64, 16) = 1024 CTAs
    clstm_tc_gemm_kernel<<<grid, 256, SMEM_BYTES>>>();

    clstm_epilogue_kernel<<<(BDIM * HDIM) / 256, 256>>>(c_x, Ub_r, Ub_i, Wb_r, Wb_i, out);
}